// round 15
// baseline (speedup 1.0000x reference)
#include <cuda_runtime.h>
#include <cuda_fp16.h>
#include <cstdint>

#define SA 136           // smem stride (halves) for activations
#define SW 136           // smem stride (halves) for weights
#define NT 512           // 16 warps
#define MROWS 256        // rows per CTA (16 warps x 16 rows)

#define B_ 512
#define LEAVES 1024
#define NINT 1023

// smem regions (bytes)
#define OFF_ALO 0u           // A-lo: 256 x SA halves = 69632
#define OFF_S0  69632u       // W slot0
#define OFF_S1  139264u      // W slot1 (also layer-0 A-hi staging)
#define OFF_MB0 208896u
#define OFF_MB1 208904u
#define SMEM_TOTAL 208912
#define WIMG_BYTES 69632u    // one layer image: [Wh 128xSW | Wl 128xSW]
#define WIMG_HALVES 34816

// Weight images: 6 layers x [hi 17408 | lo 17408] halves, exact smem layout.
__device__ __align__(16) __half g_leaf_Wimg[6 * WIMG_HALVES];
__device__ __align__(16) __half g_int_Wimg[6 * WIMG_HALVES];
__device__ float g_leaf_bias[768];
__device__ float g_int_bias[768];

// Ping-pong activation buffers for the tree (fp32, 33 channels per node)
__device__ float g_curA[(size_t)B_ * LEAVES * 33];
__device__ float g_curB[(size_t)B_ * 512 * 33];

// ---------------------------------------------------------------------------
// Prep: bake per-layer smem weight images (hi/lo fp16, SW-stride) + biases.
// ---------------------------------------------------------------------------
__global__ void prep_kernel(
    const float* __restrict__ lWin,  const float* __restrict__ lbin,
    const float* __restrict__ lWhid, const float* __restrict__ lbhid,
    const float* __restrict__ lWout, const float* __restrict__ lbout,
    const float* __restrict__ iWin,  const float* __restrict__ ibin,
    const float* __restrict__ iWhid, const float* __restrict__ ibhid,
    const float* __restrict__ iWout, const float* __restrict__ ibout)
{
    const int CHUNKS_PER_UNIT = 26112;           // 6 x 2 x 128 x 17
    const int NCHUNKS = 2 * CHUNKS_PER_UNIT;
    const int total = NCHUNKS + 1536;
    for (int idx = blockIdx.x * blockDim.x + threadIdx.x; idx < total;
         idx += gridDim.x * blockDim.x) {
        if (idx < NCHUNKS) {
            const int unit = idx / CHUNKS_PER_UNIT;
            int j = idx - unit * CHUNKS_PER_UNIT;
            const int layer = j / 4352;  j -= layer * 4352;
            const int mat   = j / 2176;  j -= mat * 2176;
            const int n     = j / 17;
            const int c0    = (j - n * 17) * 8;

            __half out8[8];
            #pragma unroll
            for (int h = 0; h < 8; ++h) {
                const int k = c0 + h;
                float v = 0.f;
                if (k < 128) {
                    if (unit == 0) {
                        if (layer == 0)      v = (k < 64) ? lWin[k * 128 + n] : 0.f;
                        else if (layer < 5)  v = lWhid[(layer - 1) * 16384 + k * 128 + n];
                        else                 v = (n < 33) ? lWout[k * 33 + n] : 0.f;
                    } else {
                        if (layer == 0)      v = (k < 98) ? iWin[k * 128 + n] : 0.f;
                        else if (layer < 5)  v = iWhid[(layer - 1) * 16384 + k * 128 + n];
                        else                 v = (n < 33) ? iWout[k * 33 + n] : 0.f;
                    }
                }
                __half hi = __float2half_rn(v);
                out8[h] = (mat == 0) ? hi : __float2half_rn(v - __half2float(hi));
            }
            size_t off = (size_t)layer * WIMG_HALVES + (size_t)mat * 17408
                       + (size_t)n * SW + c0;
            __half* dst = (unit == 0) ? g_leaf_Wimg : g_int_Wimg;
            *(uint4*)(dst + off) = *(uint4*)out8;
        } else {
            int i3 = idx - NCHUNKS;
            int j = (i3 < 768) ? i3 : i3 - 768;
            int l = j >> 7, c = j & 127;
            float v;
            if (i3 < 768) {
                if (l == 0)      v = lbin[c];
                else if (l < 5)  v = lbhid[(l - 1) * 128 + c];
                else             v = (c < 33) ? lbout[c] : 0.f;
                g_leaf_bias[j] = v;
            } else {
                if (l == 0)      v = ibin[c];
                else if (l < 5)  v = ibhid[(l - 1) * 128 + c];
                else             v = (c < 33) ? ibout[c] : 0.f;
                g_int_bias[j] = v;
            }
        }
    }
}

// ---------------------------------------------------------------------------
// PTX helpers
// ---------------------------------------------------------------------------
__device__ __forceinline__ void mma16816(float* c, const uint32_t* a,
                                         uint32_t b0, uint32_t b1)
{
    asm volatile(
        "mma.sync.aligned.m16n8k16.row.col.f32.f16.f16.f32 "
        "{%0,%1,%2,%3}, {%4,%5,%6,%7}, {%8,%9}, {%0,%1,%2,%3};\n"
        : "+f"(c[0]), "+f"(c[1]), "+f"(c[2]), "+f"(c[3])
        : "r"(a[0]), "r"(a[1]), "r"(a[2]), "r"(a[3]), "r"(b0), "r"(b1));
}

__device__ __forceinline__ void ldsm4(uint32_t* r, uint32_t addr)
{
    asm volatile("ldmatrix.sync.aligned.m8n8.x4.shared.b16 {%0,%1,%2,%3}, [%4];"
                 : "=r"(r[0]), "=r"(r[1]), "=r"(r[2]), "=r"(r[3]) : "r"(addr));
}

__device__ __forceinline__ void mbar_init(uint32_t mbar, uint32_t cnt)
{
    asm volatile("mbarrier.init.shared.b64 [%0], %1;" :: "r"(mbar), "r"(cnt) : "memory");
}
__device__ __forceinline__ void mbar_expect_tx(uint32_t mbar, uint32_t bytes)
{
    asm volatile("mbarrier.arrive.expect_tx.shared.b64 _, [%0], %1;"
                 :: "r"(mbar), "r"(bytes) : "memory");
}
__device__ __forceinline__ void bulk_g2s(uint32_t dst, const void* src,
                                         uint32_t bytes, uint32_t mbar)
{
    asm volatile(
        "cp.async.bulk.shared::cluster.global.mbarrier::complete_tx::bytes "
        "[%0], [%1], %2, [%3];"
        :: "r"(dst), "l"(src), "r"(bytes), "r"(mbar) : "memory");
}
__device__ __forceinline__ void mbar_wait(uint32_t mbar, uint32_t parity)
{
    asm volatile(
        "{\n\t.reg .pred P;\n\t"
        "WL%=:\n\t"
        "mbarrier.try_wait.parity.acquire.cta.shared::cta.b64 P, [%0], %1, 0x989680;\n\t"
        "@P bra.uni WD%=;\n\t"
        "bra.uni WL%=;\n\t"
        "WD%=:\n\t}"
        :: "r"(mbar), "r"(parity) : "memory");
}
#define FENCE_PROXY_ASYNC() asm volatile("fence.proxy.async.shared::cta;" ::: "memory")

// ---------------------------------------------------------------------------
// One kstep's MMAs over NPAIRS n16-pairs (NTILES n8 tiles), W from smem.
// wbase = uW + offW + ks*32 bytes.
// ---------------------------------------------------------------------------
template<int NPAIRS, int NTILES>
__device__ __forceinline__ void mma_pairs(
    float (&C)[16][4], const uint32_t* ah, const uint32_t* al, uint32_t wbase)
{
    #pragma unroll
    for (int p = 0; p < NPAIRS; ++p) {
        uint32_t wh[4], wl[4];
        ldsm4(wh, wbase + (uint32_t)(p * 16 * SW) * 2u);
        ldsm4(wl, wbase + (uint32_t)(p * 16 * SW) * 2u + 34816u);
        #pragma unroll
        for (int s = 0; s < 2; ++s) {
            const int t = p * 2 + s;
            if (t < NTILES) {
                mma16816(C[t], ah, wh[2 * s], wh[2 * s + 1]);
                mma16816(C[t], ah, wl[2 * s], wl[2 * s + 1]);
                mma16816(C[t], al, wh[2 * s], wh[2 * s + 1]);
            }
        }
    }
}

// ---------------------------------------------------------------------------
// Epilogue for hidden layers: C -> bias+ReLU -> A-hi regs (MMA A-fragment
// layout, the C->A handoff) + A-lo STS to own rows of the ALO region.
// ---------------------------------------------------------------------------
__device__ __forceinline__ void epilogue_hidden(
    float (&C)[16][4], uint32_t (&ahi)[8][4], __half* sAlo,
    const float* gbias, int l, int warp, int gid, int tig)
{
    const int r = warp * 16 + gid;
    #pragma unroll
    for (int ks = 0; ks < 8; ++ks) {
        #pragma unroll
        for (int s = 0; s < 2; ++s) {
            const int t = ks * 2 + s;
            const int cb = t * 8 + tig * 2;
            float b0 = gbias[l * 128 + cb];
            float b1 = gbias[l * 128 + cb + 1];
            float v0 = fmaxf(C[t][0] + b0, 0.f);
            float v1 = fmaxf(C[t][1] + b1, 0.f);
            float v2 = fmaxf(C[t][2] + b0, 0.f);
            float v3 = fmaxf(C[t][3] + b1, 0.f);
            __half h0 = __float2half_rn(v0), h1 = __float2half_rn(v1);
            __half h2 = __float2half_rn(v2), h3 = __float2half_rn(v3);
            __half2 hi01 = __halves2half2(h0, h1);
            __half2 hi23 = __halves2half2(h2, h3);
            ahi[ks][s * 2 + 0] = *(uint32_t*)&hi01;   // a0 / a2 (row gid)
            ahi[ks][s * 2 + 1] = *(uint32_t*)&hi23;   // a1 / a3 (row gid+8)
            __half e0 = __float2half_rn(v0 - __half2float(h0));
            __half e1 = __float2half_rn(v1 - __half2float(h1));
            __half e2 = __float2half_rn(v2 - __half2float(h2));
            __half e3 = __float2half_rn(v3 - __half2float(h3));
            *(__half2*)(sAlo + r * SA + cb)       = __halves2half2(e0, e1);
            *(__half2*)(sAlo + (r + 8) * SA + cb) = __halves2half2(e2, e3);
        }
    }
    __syncwarp();    // STS visible to this warp's ldmatrix next layer
}

// ---------------------------------------------------------------------------
// 6-layer MLP for 256 rows. 16 warps, warp = 16 rows x 128 cols (m16n128).
// A-hi lives in registers across layers (C->A fragment handoff); A-lo spills
// to smem (own rows). W arrives via one cp.async.bulk per layer.
// ---------------------------------------------------------------------------
template<int KS0>
__device__ __forceinline__ void run_unit(
    char* smem, const __half* gWimg, const float* gbias,
    float* gout, float* dfinal, int row0)
{
    const uint32_t sb = (uint32_t)__cvta_generic_to_shared(smem);
    __half* sAlo = (__half*)(smem + OFF_ALO);

    const int tid  = threadIdx.x;
    const int warp = tid >> 5;
    const int lane = tid & 31;
    const int gid = lane >> 2;
    const int tig = lane & 3;

    // A ldsm offset: row = warp*16 + (lane&15), col = (lane>>4)*8  (+ks*16)
    const uint32_t offA = (uint32_t)((warp * 16 + (lane & 15)) * SA
                                     + ((lane >> 4) << 3)) * 2u;
    // W ldsm offset (pair 0): row = ((lane>>4)<<3)+(lane&7), col = ((lane>>3)&1)*8
    const uint32_t offW = (uint32_t)(((((lane >> 4) << 3) + (lane & 7)) * SW)
                                     + (((lane >> 3) & 1) << 3)) * 2u;

    uint32_t ahi[8][4];
    float C[16][4];

    // ================= layer 0 (classic: A-hi in slot1, A-lo in ALO) ========
    mbar_wait(sb + OFF_MB0, 0u);
    #pragma unroll
    for (int t = 0; t < 16; ++t)
        #pragma unroll
        for (int q = 0; q < 4; ++q) C[t][q] = 0.f;
    {
        const uint32_t uAh = sb + OFF_S1 + offA;
        const uint32_t uAl = sb + OFF_ALO + offA;
        const uint32_t wb  = sb + OFF_S0 + offW;
        #pragma unroll
        for (int ks = 0; ks < KS0; ++ks) {
            uint32_t ah[4], al[4];
            ldsm4(ah, uAh + ks * 32u);
            ldsm4(al, uAl + ks * 32u);
            mma_pairs<8, 16>(C, ah, al, wb + ks * 32u);
        }
    }
    __syncthreads();   // all warps done reading slot0 (W0), slot1 (A-hi), ALO
    if (tid == 0) {
        FENCE_PROXY_ASYNC();
        mbar_expect_tx(sb + OFF_MB1, WIMG_BYTES);
        bulk_g2s(sb + OFF_S1, gWimg + WIMG_HALVES, WIMG_BYTES, sb + OFF_MB1);
        mbar_expect_tx(sb + OFF_MB0, WIMG_BYTES);
        bulk_g2s(sb + OFF_S0, gWimg + 2 * (size_t)WIMG_HALVES, WIMG_BYTES, sb + OFF_MB0);
    }
    epilogue_hidden(C, ahi, sAlo, gbias, 0, warp, gid, tig);

    // ================= layers 1..4 (reg-A) ==================================
    #pragma unroll 1
    for (int l = 1; l < 5; ++l) {
        const uint32_t uW = sb + ((l & 1) ? OFF_S1 : OFF_S0);
        const uint32_t mb = sb + ((l & 1) ? OFF_MB1 : OFF_MB0);
        mbar_wait(mb, (uint32_t)((l >> 1) & 1));

        #pragma unroll
        for (int t = 0; t < 16; ++t)
            #pragma unroll
            for (int q = 0; q < 4; ++q) C[t][q] = 0.f;

        const uint32_t uAl = sb + OFF_ALO + offA;
        const uint32_t wb  = uW + offW;
        #pragma unroll
        for (int ks = 0; ks < 8; ++ks) {
            uint32_t al[4];
            ldsm4(al, uAl + ks * 32u);
            mma_pairs<8, 16>(C, ahi[ks], al, wb + ks * 32u);
        }
        __syncthreads();   // all warps done reading W(l) -> slot reusable
        if (l <= 3 && tid == 0) {
            FENCE_PROXY_ASYNC();
            mbar_expect_tx(mb, WIMG_BYTES);
            bulk_g2s(uW, gWimg + (size_t)(l + 2) * WIMG_HALVES, WIMG_BYTES, mb);
        }
        epilogue_hidden(C, ahi, sAlo, gbias, l, warp, gid, tig);
    }

    // ================= layer 5 (output, Np=40 -> 5 tiles) ===================
    mbar_wait(sb + OFF_MB1, 0u);
    #pragma unroll
    for (int t = 0; t < 16; ++t)
        #pragma unroll
        for (int q = 0; q < 4; ++q) C[t][q] = 0.f;
    {
        const uint32_t uAl = sb + OFF_ALO + offA;
        const uint32_t wb  = sb + OFF_S1 + offW;
        #pragma unroll
        for (int ks = 0; ks < 8; ++ks) {
            uint32_t al[4];
            ldsm4(al, uAl + ks * 32u);
            mma_pairs<3, 5>(C, ahi[ks], al, wb + ks * 32u);
        }
    }
    // output epilogue
    {
        const int r = warp * 16 + gid;
        #pragma unroll
        for (int t = 0; t < 5; ++t) {
            const int cb = t * 8 + tig * 2;
            float b0 = gbias[640 + cb];
            float b1 = gbias[640 + cb + 1];
            float v0 = C[t][0] + b0;
            float v1 = C[t][1] + b1;
            float v2 = C[t][2] + b0;
            float v3 = C[t][3] + b1;
            if (dfinal) {
                if (cb == 0) {
                    dfinal[row0 + r]     = v0;
                    dfinal[row0 + r + 8] = v2;
                }
            } else {
                size_t ro = (size_t)(row0 + r) * 33;
                size_t r8 = (size_t)(row0 + r + 8) * 33;
                if (cb < 33)     { gout[ro + cb]     = v0; gout[r8 + cb]     = v2; }
                if (cb + 1 < 33) { gout[ro + cb + 1] = v1; gout[r8 + cb + 1] = v3; }
            }
        }
    }
}

// ---------------------------------------------------------------------------
// common start: init mbars, launch W0 bulk
// ---------------------------------------------------------------------------
__device__ __forceinline__ void stage_start(uint32_t sb, const __half* gWimg)
{
    if (threadIdx.x == 0) {
        mbar_init(sb + OFF_MB0, 1);
        mbar_init(sb + OFF_MB1, 1);
    }
    __syncthreads();
    if (threadIdx.x == 0) {
        mbar_expect_tx(sb + OFF_MB0, WIMG_BYTES);
        bulk_g2s(sb + OFF_S0, gWimg, WIMG_BYTES, sb + OFF_MB0);
    }
}

// ---------------------------------------------------------------------------
// Leaf kernel: 256 rows/CTA of leaf_feat (K=64 -> 4 ksteps)
// ---------------------------------------------------------------------------
__global__ void __launch_bounds__(NT, 1)
leaf_kernel(const float* __restrict__ leaf_feat, float* __restrict__ curOut)
{
    extern __shared__ char smem[];
    const uint32_t sb = (uint32_t)__cvta_generic_to_shared(smem);
    __half* sAh = (__half*)(smem + OFF_S1);
    __half* sAl = (__half*)(smem + OFF_ALO);

    stage_start(sb, g_leaf_Wimg);

    const int row0 = blockIdx.x * MROWS;
    for (int i = threadIdx.x; i < MROWS * 16; i += NT) {
        int r = i >> 4, c4 = i & 15;
        float4 v = ((const float4*)(leaf_feat + (size_t)(row0 + r) * 64))[c4];
        int c = c4 * 4;
        __half h0 = __float2half_rn(v.x), h1 = __float2half_rn(v.y);
        __half h2 = __float2half_rn(v.z), h3 = __float2half_rn(v.w);
        __half e0 = __float2half_rn(v.x - __half2float(h0));
        __half e1 = __float2half_rn(v.y - __half2float(h1));
        __half e2 = __float2half_rn(v.z - __half2float(h2));
        __half e3 = __float2half_rn(v.w - __half2float(h3));
        *(__half2*)(sAh + r * SA + c)     = __halves2half2(h0, h1);
        *(__half2*)(sAh + r * SA + c + 2) = __halves2half2(h2, h3);
        *(__half2*)(sAl + r * SA + c)     = __halves2half2(e0, e1);
        *(__half2*)(sAl + r * SA + c + 2) = __halves2half2(e2, e3);
    }
    __syncthreads();

    run_unit<4>(smem, g_leaf_Wimg, g_leaf_bias, curOut, nullptr, row0);
}

// ---------------------------------------------------------------------------
// Tree-level kernel: builds [feat(32) | child0(33) | child1(33) | pad] rows
// (K=98 padded to 112 -> 7 ksteps)
// ---------------------------------------------------------------------------
__global__ void __launch_bounds__(NT, 1)
int_kernel(const float* __restrict__ int_feat, const float* __restrict__ prev,
           float* __restrict__ curOut, int log2n, float* dfinal)
{
    extern __shared__ char smem[];
    const uint32_t sb = (uint32_t)__cvta_generic_to_shared(smem);
    __half* sAh = (__half*)(smem + OFF_S1);
    __half* sAl = (__half*)(smem + OFF_ALO);

    stage_start(sb, g_int_Wimg);

    const int row0 = blockIdx.x * MROWS;
    const int n = 1 << log2n;

    for (int i = threadIdx.x; i < MROWS * 112; i += NT) {
        int r = i / 112, c = i - r * 112;
        int rowg = row0 + r;
        int b  = rowg >> log2n;
        int ii = rowg & (n - 1);
        float v;
        if (c < 32) {
            v = int_feat[((size_t)b * NINT + (n - 1) + ii) * 32 + c];
        } else if (c < 98) {
            v = prev[((size_t)b * (n << 1) + (ii << 1)) * 33 + (c - 32)];
        } else {
            v = 0.f;
        }
        __half h = __float2half_rn(v);
        __half e = __float2half_rn(v - __half2float(h));
        sAh[r * SA + c] = h;
        sAl[r * SA + c] = e;
    }
    __syncthreads();

    run_unit<7>(smem, g_int_Wimg, g_int_bias, curOut, dfinal, row0);
}

// ---------------------------------------------------------------------------
extern "C" void kernel_launch(void* const* d_in, const int* in_sizes, int n_in,
                              void* d_out, int out_size)
{
    const float* leaf_feat = (const float*)d_in[0];
    const float* int_feat  = (const float*)d_in[1];
    const float* lWin  = (const float*)d_in[2];
    const float* lbin  = (const float*)d_in[3];
    const float* lWhid = (const float*)d_in[4];
    const float* lbhid = (const float*)d_in[5];
    const float* lWout = (const float*)d_in[6];
    const float* lbout = (const float*)d_in[7];
    const float* iWin  = (const float*)d_in[8];
    const float* ibin  = (const float*)d_in[9];
    const float* iWhid = (const float*)d_in[10];
    const float* ibhid = (const float*)d_in[11];
    const float* iWout = (const float*)d_in[12];
    const float* ibout = (const float*)d_in[13];
    float* out = (float*)d_out;

    cudaFuncSetAttribute(leaf_kernel, cudaFuncAttributeMaxDynamicSharedMemorySize, SMEM_TOTAL);
    cudaFuncSetAttribute(int_kernel,  cudaFuncAttributeMaxDynamicSharedMemorySize, SMEM_TOTAL);

    float *curA = nullptr, *curB = nullptr;
    cudaGetSymbolAddress((void**)&curA, g_curA);
    cudaGetSymbolAddress((void**)&curB, g_curB);

    prep_kernel<<<256, 256>>>(lWin, lbin, lWhid, lbhid, lWout, lbout,
                              iWin, ibin, iWhid, ibhid, iWout, ibout);

    leaf_kernel<<<(B_ * LEAVES) / MROWS, NT, SMEM_TOTAL>>>(leaf_feat, curA);

    float* pin = curA;
    float* pout = curB;
    for (int d = 9; d >= 1; --d) {
        int rows = B_ << d;
        int_kernel<<<rows / MROWS, NT, SMEM_TOTAL>>>(int_feat, pin, pout, d, nullptr);
        float* t = pin; pin = pout; pout = t;
    }
    int_kernel<<<B_ / MROWS, NT, SMEM_TOTAL>>>(int_feat, pin, pout, 0, out);
}

// round 16
// speedup vs baseline: 1.0544x; 1.0544x over previous
#include <cuda_runtime.h>
#include <cuda_fp16.h>
#include <cstdint>

#define SA 136           // smem stride (halves) for activations
#define SW 136           // smem stride (halves) for weights
#define NT 1024          // 32 warps
#define MROWS 256        // rows per CTA (16 wm-groups x 16 rows)

#define B_ 512
#define LEAVES 1024
#define NINT 1023

// smem regions (bytes)
#define OFF_AH  0u           // A-hi: 256 x SA halves = 69632
#define OFF_AL  69632u       // A-lo
#define OFF_W   139264u      // single W buffer: [Wh 128xSW | Wl 128xSW]
#define OFF_MB  208896u
#define SMEM_TOTAL 208912
#define WIMG_BYTES 69632u
#define WIMG_HALVES 34816

// Weight images: 6 layers x [hi 17408 | lo 17408] halves, exact smem layout.
__device__ __align__(16) __half g_leaf_Wimg[6 * WIMG_HALVES];
__device__ __align__(16) __half g_int_Wimg[6 * WIMG_HALVES];
__device__ float g_leaf_bias[768];
__device__ float g_int_bias[768];

// Ping-pong activation buffers for the tree (fp32, 33 channels per node)
__device__ float g_curA[(size_t)B_ * LEAVES * 33];
__device__ float g_curB[(size_t)B_ * 512 * 33];

// ---------------------------------------------------------------------------
// Prep: bake per-layer smem weight images (hi/lo fp16, SW-stride) + biases.
// ---------------------------------------------------------------------------
__global__ void prep_kernel(
    const float* __restrict__ lWin,  const float* __restrict__ lbin,
    const float* __restrict__ lWhid, const float* __restrict__ lbhid,
    const float* __restrict__ lWout, const float* __restrict__ lbout,
    const float* __restrict__ iWin,  const float* __restrict__ ibin,
    const float* __restrict__ iWhid, const float* __restrict__ ibhid,
    const float* __restrict__ iWout, const float* __restrict__ ibout)
{
    const int CHUNKS_PER_UNIT = 26112;           // 6 x 2 x 128 x 17
    const int NCHUNKS = 2 * CHUNKS_PER_UNIT;
    const int total = NCHUNKS + 1536;
    for (int idx = blockIdx.x * blockDim.x + threadIdx.x; idx < total;
         idx += gridDim.x * blockDim.x) {
        if (idx < NCHUNKS) {
            const int unit = idx / CHUNKS_PER_UNIT;
            int j = idx - unit * CHUNKS_PER_UNIT;
            const int layer = j / 4352;  j -= layer * 4352;
            const int mat   = j / 2176;  j -= mat * 2176;
            const int n     = j / 17;
            const int c0    = (j - n * 17) * 8;

            __half out8[8];
            #pragma unroll
            for (int h = 0; h < 8; ++h) {
                const int k = c0 + h;
                float v = 0.f;
                if (k < 128) {
                    if (unit == 0) {
                        if (layer == 0)      v = (k < 64) ? lWin[k * 128 + n] : 0.f;
                        else if (layer < 5)  v = lWhid[(layer - 1) * 16384 + k * 128 + n];
                        else                 v = (n < 33) ? lWout[k * 33 + n] : 0.f;
                    } else {
                        if (layer == 0)      v = (k < 98) ? iWin[k * 128 + n] : 0.f;
                        else if (layer < 5)  v = iWhid[(layer - 1) * 16384 + k * 128 + n];
                        else                 v = (n < 33) ? iWout[k * 33 + n] : 0.f;
                    }
                }
                __half hi = __float2half_rn(v);
                out8[h] = (mat == 0) ? hi : __float2half_rn(v - __half2float(hi));
            }
            size_t off = (size_t)layer * WIMG_HALVES + (size_t)mat * 17408
                       + (size_t)n * SW + c0;
            __half* dst = (unit == 0) ? g_leaf_Wimg : g_int_Wimg;
            *(uint4*)(dst + off) = *(uint4*)out8;
        } else {
            int i3 = idx - NCHUNKS;
            int j = (i3 < 768) ? i3 : i3 - 768;
            int l = j >> 7, c = j & 127;
            float v;
            if (i3 < 768) {
                if (l == 0)      v = lbin[c];
                else if (l < 5)  v = lbhid[(l - 1) * 128 + c];
                else             v = (c < 33) ? lbout[c] : 0.f;
                g_leaf_bias[j] = v;
            } else {
                if (l == 0)      v = ibin[c];
                else if (l < 5)  v = ibhid[(l - 1) * 128 + c];
                else             v = (c < 33) ? ibout[c] : 0.f;
                g_int_bias[j] = v;
            }
        }
    }
}

// ---------------------------------------------------------------------------
// PTX helpers
// ---------------------------------------------------------------------------
__device__ __forceinline__ void mma16816(float* c, const uint32_t* a,
                                         uint32_t b0, uint32_t b1)
{
    asm volatile(
        "mma.sync.aligned.m16n8k16.row.col.f32.f16.f16.f32 "
        "{%0,%1,%2,%3}, {%4,%5,%6,%7}, {%8,%9}, {%0,%1,%2,%3};\n"
        : "+f"(c[0]), "+f"(c[1]), "+f"(c[2]), "+f"(c[3])
        : "r"(a[0]), "r"(a[1]), "r"(a[2]), "r"(a[3]), "r"(b0), "r"(b1));
}

__device__ __forceinline__ void ldsm4(uint32_t* r, uint32_t addr)
{
    asm volatile("ldmatrix.sync.aligned.m8n8.x4.shared.b16 {%0,%1,%2,%3}, [%4];"
                 : "=r"(r[0]), "=r"(r[1]), "=r"(r[2]), "=r"(r[3]) : "r"(addr));
}

__device__ __forceinline__ void mbar_init(uint32_t mbar, uint32_t cnt)
{
    asm volatile("mbarrier.init.shared.b64 [%0], %1;" :: "r"(mbar), "r"(cnt) : "memory");
}
__device__ __forceinline__ void mbar_expect_tx(uint32_t mbar, uint32_t bytes)
{
    asm volatile("mbarrier.arrive.expect_tx.shared.b64 _, [%0], %1;"
                 :: "r"(mbar), "r"(bytes) : "memory");
}
__device__ __forceinline__ void bulk_g2s(uint32_t dst, const void* src,
                                         uint32_t bytes, uint32_t mbar)
{
    asm volatile(
        "cp.async.bulk.shared::cluster.global.mbarrier::complete_tx::bytes "
        "[%0], [%1], %2, [%3];"
        :: "r"(dst), "l"(src), "r"(bytes), "r"(mbar) : "memory");
}
__device__ __forceinline__ void mbar_wait(uint32_t mbar, uint32_t parity)
{
    asm volatile(
        "{\n\t.reg .pred P;\n\t"
        "WL%=:\n\t"
        "mbarrier.try_wait.parity.acquire.cta.shared::cta.b64 P, [%0], %1, 0x989680;\n\t"
        "@P bra.uni WD%=;\n\t"
        "bra.uni WL%=;\n\t"
        "WD%=:\n\t}"
        :: "r"(mbar), "r"(parity) : "memory");
}
#define FENCE_PROXY_ASYNC() asm volatile("fence.proxy.async.shared::cta;" ::: "memory")

// ---------------------------------------------------------------------------
// One kstep over NTILES n8-tiles (warp covers n = wn*64 .. +NTILES*8).
// W pairs loaded sequentially (one live pair) to stay under 64 regs.
// ---------------------------------------------------------------------------
template<int NTILES>
__device__ __forceinline__ void mma_kstep(
    float (&C)[8][4], uint32_t aAh, uint32_t aAl, uint32_t wb)
{
    uint32_t ah[4], al[4];
    ldsm4(ah, aAh);
    ldsm4(al, aAl);
    #pragma unroll
    for (int p = 0; p < (NTILES + 1) / 2; ++p) {
        uint32_t wh[4], wl[4];
        ldsm4(wh, wb + (uint32_t)(p * 16 * SW) * 2u);
        ldsm4(wl, wb + (uint32_t)(p * 16 * SW) * 2u + 34816u);
        #pragma unroll
        for (int s = 0; s < 2; ++s) {
            const int t = p * 2 + s;
            if (t < NTILES) {
                mma16816(C[t], ah, wh[2 * s], wh[2 * s + 1]);
                mma16816(C[t], ah, wl[2 * s], wl[2 * s + 1]);
                mma16816(C[t], al, wh[2 * s], wh[2 * s + 1]);
            }
        }
    }
}

template<int KSTEPS, int NTILES>
__device__ __forceinline__ void mma_layer(
    float (&C)[8][4], uint32_t aAh, uint32_t aAl, uint32_t wb)
{
    #pragma unroll
    for (int ks = 0; ks < KSTEPS; ++ks)
        mma_kstep<NTILES>(C, aAh + ks * 32u, aAl + ks * 32u, wb + ks * 32u);
}

// ---------------------------------------------------------------------------
// 6-layer MLP for 256 rows in smem. 32 warps as 16 wm-groups x 2 wn-groups;
// warp tile m16n64. Single W buffer fed by one cp.async.bulk per layer.
// ---------------------------------------------------------------------------
template<int KS0>
__device__ __forceinline__ void run_unit(
    char* smem, const __half* gWimg, const float* gbias,
    float* gout, float* dfinal, int row0)
{
    const uint32_t sb = (uint32_t)__cvta_generic_to_shared(smem);
    __half* sAh = (__half*)(smem + OFF_AH);
    __half* sAl = (__half*)(smem + OFF_AL);
    const uint32_t mb = sb + OFF_MB;

    const int tid  = threadIdx.x;
    const int warp = tid >> 5;
    const int lane = tid & 31;
    const int wm = warp >> 1;      // 0..15 (16-row block)
    const int wn = warp & 1;       // 0..1  (64-col block)
    const int gid = lane >> 2;
    const int tig = lane & 3;

    // A ldsm offset: row = wm*16 + (lane&15), col = (lane>>4)*8
    const uint32_t offA = (uint32_t)((wm * 16 + (lane & 15)) * SA
                                     + ((lane >> 4) << 3)) * 2u;
    // W ldsm offset (pair 0): n-row = wn*64 + ((lane>>4)<<3)+(lane&7)
    const uint32_t offW = (uint32_t)((wn * 64 + ((lane >> 4) << 3) + (lane & 7)) * SW
                                     + (((lane >> 3) & 1) << 3)) * 2u;

    #pragma unroll
    for (int l = 0; l < 6; ++l) {
        mbar_wait(mb, (uint32_t)(l & 1));          // W(l) image arrived

        float C[8][4];
        #pragma unroll
        for (int t = 0; t < 8; ++t)
            #pragma unroll
            for (int q = 0; q < 4; ++q) C[t][q] = 0.f;

        const uint32_t aAh = sb + OFF_AH + offA;
        const uint32_t aAl = sb + OFF_AL + offA;
        const uint32_t wb  = sb + OFF_W + offW;

        if (l == 0)       mma_layer<KS0, 8>(C, aAh, aAl, wb);
        else if (l < 5)   mma_layer<8, 8>(C, aAh, aAl, wb);
        else if (wn == 0) mma_layer<8, 5>(C, aAh, aAl, wb);

        __syncthreads();           // all reads of A(l) and W(l) done

        // single-thread bulk copy of W(l+1) into the (now free) W buffer;
        // overlaps the epilogue + trailing barrier.
        if (l < 5 && tid == 0) {
            FENCE_PROXY_ASYNC();
            mbar_expect_tx(mb, WIMG_BYTES);
            bulk_g2s(sb + OFF_W, gWimg + (size_t)(l + 1) * WIMG_HALVES,
                     WIMG_BYTES, mb);
        }

        // ---- epilogue ----
        if (l < 5) {
            const int r = wm * 16 + gid;
            #pragma unroll
            for (int t = 0; t < 8; ++t) {
                const int cb = wn * 64 + t * 8 + tig * 2;
                float b0 = gbias[l * 128 + cb];
                float b1 = gbias[l * 128 + cb + 1];
                float v0 = fmaxf(C[t][0] + b0, 0.f);
                float v1 = fmaxf(C[t][1] + b1, 0.f);
                float v2 = fmaxf(C[t][2] + b0, 0.f);
                float v3 = fmaxf(C[t][3] + b1, 0.f);
                __half h0 = __float2half_rn(v0), h1 = __float2half_rn(v1);
                __half h2 = __float2half_rn(v2), h3 = __float2half_rn(v3);
                __half e0 = __float2half_rn(v0 - __half2float(h0));
                __half e1 = __float2half_rn(v1 - __half2float(h1));
                __half e2 = __float2half_rn(v2 - __half2float(h2));
                __half e3 = __float2half_rn(v3 - __half2float(h3));
                *(__half2*)(sAh + r * SA + cb)       = __halves2half2(h0, h1);
                *(__half2*)(sAh + (r + 8) * SA + cb) = __halves2half2(h2, h3);
                *(__half2*)(sAl + r * SA + cb)       = __halves2half2(e0, e1);
                *(__half2*)(sAl + (r + 8) * SA + cb) = __halves2half2(e2, e3);
            }
            __syncthreads();       // A(l+1) visible to all warps
        } else if (wn == 0) {
            const int r = wm * 16 + gid;
            #pragma unroll
            for (int t = 0; t < 5; ++t) {
                const int cb = t * 8 + tig * 2;
                float b0 = gbias[640 + cb];
                float b1 = gbias[640 + cb + 1];
                float v0 = C[t][0] + b0;
                float v1 = C[t][1] + b1;
                float v2 = C[t][2] + b0;
                float v3 = C[t][3] + b1;
                if (dfinal) {
                    if (cb == 0) {
                        dfinal[row0 + r]     = v0;
                        dfinal[row0 + r + 8] = v2;
                    }
                } else {
                    size_t ro = (size_t)(row0 + r) * 33;
                    size_t r8 = (size_t)(row0 + r + 8) * 33;
                    if (cb < 33)     { gout[ro + cb]     = v0; gout[r8 + cb]     = v2; }
                    if (cb + 1 < 33) { gout[ro + cb + 1] = v1; gout[r8 + cb + 1] = v3; }
                }
            }
        }
    }
}

// ---------------------------------------------------------------------------
// common start: init mbar, launch W0 bulk
// ---------------------------------------------------------------------------
__device__ __forceinline__ void stage_start(uint32_t sb, const __half* gWimg)
{
    if (threadIdx.x == 0) mbar_init(sb + OFF_MB, 1);
    __syncthreads();
    if (threadIdx.x == 0) {
        mbar_expect_tx(sb + OFF_MB, WIMG_BYTES);
        bulk_g2s(sb + OFF_W, gWimg, WIMG_BYTES, sb + OFF_MB);
    }
}

// ---------------------------------------------------------------------------
// Leaf kernel: 256 rows/CTA of leaf_feat (K=64 -> 4 ksteps)
// ---------------------------------------------------------------------------
__global__ void __launch_bounds__(NT, 1)
leaf_kernel(const float* __restrict__ leaf_feat, float* __restrict__ curOut)
{
    extern __shared__ char smem[];
    const uint32_t sb = (uint32_t)__cvta_generic_to_shared(smem);
    __half* sAh = (__half*)(smem + OFF_AH);
    __half* sAl = (__half*)(smem + OFF_AL);

    stage_start(sb, g_leaf_Wimg);

    const int row0 = blockIdx.x * MROWS;
    for (int i = threadIdx.x; i < MROWS * 16; i += NT) {
        int r = i >> 4, c4 = i & 15;
        float4 v = ((const float4*)(leaf_feat + (size_t)(row0 + r) * 64))[c4];
        int c = c4 * 4;
        __half h0 = __float2half_rn(v.x), h1 = __float2half_rn(v.y);
        __half h2 = __float2half_rn(v.z), h3 = __float2half_rn(v.w);
        __half e0 = __float2half_rn(v.x - __half2float(h0));
        __half e1 = __float2half_rn(v.y - __half2float(h1));
        __half e2 = __float2half_rn(v.z - __half2float(h2));
        __half e3 = __float2half_rn(v.w - __half2float(h3));
        *(__half2*)(sAh + r * SA + c)     = __halves2half2(h0, h1);
        *(__half2*)(sAh + r * SA + c + 2) = __halves2half2(h2, h3);
        *(__half2*)(sAl + r * SA + c)     = __halves2half2(e0, e1);
        *(__half2*)(sAl + r * SA + c + 2) = __halves2half2(e2, e3);
    }
    __syncthreads();

    run_unit<4>(smem, g_leaf_Wimg, g_leaf_bias, curOut, nullptr, row0);
}

// ---------------------------------------------------------------------------
// Tree-level kernel: builds [feat(32) | child0(33) | child1(33) | pad] rows
// (K=98 padded to 112 -> 7 ksteps)
// ---------------------------------------------------------------------------
__global__ void __launch_bounds__(NT, 1)
int_kernel(const float* __restrict__ int_feat, const float* __restrict__ prev,
           float* __restrict__ curOut, int log2n, float* dfinal)
{
    extern __shared__ char smem[];
    const uint32_t sb = (uint32_t)__cvta_generic_to_shared(smem);
    __half* sAh = (__half*)(smem + OFF_AH);
    __half* sAl = (__half*)(smem + OFF_AL);

    stage_start(sb, g_int_Wimg);

    const int row0 = blockIdx.x * MROWS;
    const int n = 1 << log2n;

    for (int i = threadIdx.x; i < MROWS * 112; i += NT) {
        int r = i / 112, c = i - r * 112;
        int rowg = row0 + r;
        int b  = rowg >> log2n;
        int ii = rowg & (n - 1);
        float v;
        if (c < 32) {
            v = int_feat[((size_t)b * NINT + (n - 1) + ii) * 32 + c];
        } else if (c < 98) {
            v = prev[((size_t)b * (n << 1) + (ii << 1)) * 33 + (c - 32)];
        } else {
            v = 0.f;
        }
        __half h = __float2half_rn(v);
        __half e = __float2half_rn(v - __half2float(h));
        sAh[r * SA + c] = h;
        sAl[r * SA + c] = e;
    }
    __syncthreads();

    run_unit<7>(smem, g_int_Wimg, g_int_bias, curOut, dfinal, row0);
}

// ---------------------------------------------------------------------------
extern "C" void kernel_launch(void* const* d_in, const int* in_sizes, int n_in,
                              void* d_out, int out_size)
{
    const float* leaf_feat = (const float*)d_in[0];
    const float* int_feat  = (const float*)d_in[1];
    const float* lWin  = (const float*)d_in[2];
    const float* lbin  = (const float*)d_in[3];
    const float* lWhid = (const float*)d_in[4];
    const float* lbhid = (const float*)d_in[5];
    const float* lWout = (const float*)d_in[6];
    const float* lbout = (const float*)d_in[7];
    const float* iWin  = (const float*)d_in[8];
    const float* ibin  = (const float*)d_in[9];
    const float* iWhid = (const float*)d_in[10];
    const float* ibhid = (const float*)d_in[11];
    const float* iWout = (const float*)d_in[12];
    const float* ibout = (const float*)d_in[13];
    float* out = (float*)d_out;

    cudaFuncSetAttribute(leaf_kernel, cudaFuncAttributeMaxDynamicSharedMemorySize, SMEM_TOTAL);
    cudaFuncSetAttribute(int_kernel,  cudaFuncAttributeMaxDynamicSharedMemorySize, SMEM_TOTAL);

    float *curA = nullptr, *curB = nullptr;
    cudaGetSymbolAddress((void**)&curA, g_curA);
    cudaGetSymbolAddress((void**)&curB, g_curB);

    prep_kernel<<<256, 256>>>(lWin, lbin, lWhid, lbhid, lWout, lbout,
                              iWin, ibin, iWhid, ibhid, iWout, ibout);

    leaf_kernel<<<(B_ * LEAVES) / MROWS, NT, SMEM_TOTAL>>>(leaf_feat, curA);

    float* pin = curA;
    float* pout = curB;
    for (int d = 9; d >= 1; --d) {
        int rows = B_ << d;
        int_kernel<<<rows / MROWS, NT, SMEM_TOTAL>>>(int_feat, pin, pout, d, nullptr);
        float* t = pin; pin = pout; pout = t;
    }
    int_kernel<<<B_ / MROWS, NT, SMEM_TOTAL>>>(int_feat, pin, pout, 0, out);
}